// round 1
// baseline (speedup 1.0000x reference)
#include <cuda_runtime.h>

// L1Loss: out = mean(|yhat - y|) over 64*128*4096 fp32 elements.
// Pure HBM-bound streaming reduction.

__global__ void l1_zero_kernel(float* out) {
    out[0] = 0.0f;
}

__global__ void __launch_bounds__(256) l1_reduce_kernel(
    const float4* __restrict__ a,
    const float4* __restrict__ b,
    float* __restrict__ out,
    int n4,            // number of float4 elements
    int n_tail,        // scalar elements after n4*4
    float inv_n)
{
    float acc = 0.0f;

    int idx = blockIdx.x * blockDim.x + threadIdx.x;
    int stride = gridDim.x * blockDim.x;

    for (int i = idx; i < n4; i += stride) {
        float4 x = a[i];
        float4 y = b[i];
        acc += fabsf(x.x - y.x);
        acc += fabsf(x.y - y.y);
        acc += fabsf(x.z - y.z);
        acc += fabsf(x.w - y.w);
    }

    // Scalar tail (N not divisible by 4) — handled by first few threads of block 0.
    if (blockIdx.x == 0 && threadIdx.x < n_tail) {
        const float* af = (const float*)a;
        const float* bf = (const float*)b;
        int i = n4 * 4 + threadIdx.x;
        acc += fabsf(af[i] - bf[i]);
    }

    // Warp reduction
    #pragma unroll
    for (int o = 16; o > 0; o >>= 1)
        acc += __shfl_down_sync(0xffffffffu, acc, o);

    __shared__ float smem[8];
    int lane = threadIdx.x & 31;
    int wid  = threadIdx.x >> 5;
    if (lane == 0) smem[wid] = acc;
    __syncthreads();

    if (threadIdx.x < 8) {
        float v = smem[threadIdx.x];
        #pragma unroll
        for (int o = 4; o > 0; o >>= 1)
            v += __shfl_down_sync(0xffu, v, o);
        if (threadIdx.x == 0)
            atomicAdd(out, v * inv_n);
    }
}

extern "C" void kernel_launch(void* const* d_in, const int* in_sizes, int n_in,
                              void* d_out, int out_size)
{
    const float* yhat = (const float*)d_in[0];
    const float* y    = (const float*)d_in[1];
    float* out = (float*)d_out;

    long long n = in_sizes[0];
    int n4 = (int)(n / 4);
    int n_tail = (int)(n - (long long)n4 * 4);
    float inv_n = 1.0f / (float)n;

    l1_zero_kernel<<<1, 1>>>(out);

    const int threads = 256;
    const int blocks = 2368;  // 16 waves-worth of CTAs on 148 SMs
    l1_reduce_kernel<<<blocks, threads>>>(
        (const float4*)yhat, (const float4*)y, out, n4, n_tail, inv_n);
}

// round 2
// speedup vs baseline: 1.0051x; 1.0051x over previous
#include <cuda_runtime.h>

// L1Loss: out = mean(|yhat - y|) over 64*128*4096 fp32 elements.
// Pure HBM-bound streaming reduction. R2: unroll x4 front-batched loads
// (MLP_p1 = 8 LDG.128), single-wave grid.

__global__ void l1_zero_kernel(float* out) {
    out[0] = 0.0f;
}

__global__ void __launch_bounds__(256, 4) l1_reduce_kernel(
    const float4* __restrict__ a,
    const float4* __restrict__ b,
    float* __restrict__ out,
    int n4,            // number of float4 elements
    int n_tail,        // scalar elements after n4*4
    float inv_n)
{
    float acc0 = 0.0f, acc1 = 0.0f, acc2 = 0.0f, acc3 = 0.0f;

    const int idx    = blockIdx.x * blockDim.x + threadIdx.x;
    const int stride = gridDim.x * blockDim.x;

    int i = idx;
    // Main loop: 4 float4 per pointer per iteration, all 8 loads front-batched.
    for (; i + 3 * stride < n4; i += 4 * stride) {
        float4 a0 = a[i];
        float4 a1 = a[i +     stride];
        float4 a2 = a[i + 2 * stride];
        float4 a3 = a[i + 3 * stride];
        float4 b0 = b[i];
        float4 b1 = b[i +     stride];
        float4 b2 = b[i + 2 * stride];
        float4 b3 = b[i + 3 * stride];

        acc0 += fabsf(a0.x - b0.x) + fabsf(a0.y - b0.y)
              + fabsf(a0.z - b0.z) + fabsf(a0.w - b0.w);
        acc1 += fabsf(a1.x - b1.x) + fabsf(a1.y - b1.y)
              + fabsf(a1.z - b1.z) + fabsf(a1.w - b1.w);
        acc2 += fabsf(a2.x - b2.x) + fabsf(a2.y - b2.y)
              + fabsf(a2.z - b2.z) + fabsf(a2.w - b2.w);
        acc3 += fabsf(a3.x - b3.x) + fabsf(a3.y - b3.y)
              + fabsf(a3.z - b3.z) + fabsf(a3.w - b3.w);
    }
    // Remainder float4s
    for (; i < n4; i += stride) {
        float4 x = a[i];
        float4 y = b[i];
        acc0 += fabsf(x.x - y.x) + fabsf(x.y - y.y)
              + fabsf(x.z - y.z) + fabsf(x.w - y.w);
    }

    // Scalar tail (N not divisible by 4)
    if (blockIdx.x == 0 && threadIdx.x < n_tail) {
        const float* af = (const float*)a;
        const float* bf = (const float*)b;
        int t = n4 * 4 + threadIdx.x;
        acc0 += fabsf(af[t] - bf[t]);
    }

    float acc = (acc0 + acc1) + (acc2 + acc3);

    // Warp reduction
    #pragma unroll
    for (int o = 16; o > 0; o >>= 1)
        acc += __shfl_down_sync(0xffffffffu, acc, o);

    __shared__ float smem[8];
    int lane = threadIdx.x & 31;
    int wid  = threadIdx.x >> 5;
    if (lane == 0) smem[wid] = acc;
    __syncthreads();

    if (threadIdx.x < 8) {
        float v = smem[threadIdx.x];
        #pragma unroll
        for (int o = 4; o > 0; o >>= 1)
            v += __shfl_down_sync(0xffu, v, o);
        if (threadIdx.x == 0)
            atomicAdd(out, v * inv_n);
    }
}

extern "C" void kernel_launch(void* const* d_in, const int* in_sizes, int n_in,
                              void* d_out, int out_size)
{
    const float* yhat = (const float*)d_in[0];
    const float* y    = (const float*)d_in[1];
    float* out = (float*)d_out;

    long long n = in_sizes[0];
    int n4 = (int)(n / 4);
    int n_tail = (int)(n - (long long)n4 * 4);
    float inv_n = 1.0f / (float)n;

    l1_zero_kernel<<<1, 1>>>(out);

    const int threads = 256;
    const int blocks = 592;  // 148 SMs x 4 CTAs -> single wave at occ 4
    l1_reduce_kernel<<<blocks, threads>>>(
        (const float4*)yhat, (const float4*)y, out, n4, n_tail, inv_n);
}